// round 1
// baseline (speedup 1.0000x reference)
#include <cuda_runtime.h>

// SSIM loss: 16x3x512x512 f32 images, 11x11 Gaussian (sigma=1.5, separable).
// Single fused kernel: per-(plane,tile) H-conv of {x,y,xx,yy,xy} into smem,
// V-conv in registers, SSIM map, block-partial sums; tiny reduce kernel.

#define IMH 512
#define IMW 512
#define TILE_W 64
#define TILE_H 32
#define SROWS 42            // TILE_H + 10 halo rows
#define SCOLS 80            // c0-8 .. c0+71 (float4 aligned staging)
#define HSTRIDE (SROWS * TILE_W)   // 2688 floats per quantity plane
#define NBLK (8 * 16 * 48)         // 6144 tiles
#define SMEM_FLOATS (2 * SROWS * SCOLS + 5 * SROWS * TILE_W)  // 20160
#define SMEM_BYTES (SMEM_FLOATS * 4)                          // 80640

__device__ float g_partials[NBLK];

// 1D Gaussian taps, sigma = 1.5, ws = 11, normalized. Hardcoded as literals so
// ptxas emits FFMA-imm (rt=1 per SMSP, 2x the 3-reg FFMA rate on sm_103a).
static __device__ constexpr float Gw[11] = {
    0.00102838f, 0.00759876f, 0.03600078f, 0.10936070f, 0.21300553f,
    0.26601172f,
    0.21300553f, 0.10936070f, 0.03600078f, 0.00759876f, 0.00102838f};

extern "C" __global__ void __launch_bounds__(256, 2)
ssim_main(const float* __restrict__ gx, const float* __restrict__ gy) {
    extern __shared__ float sm[];
    float* sx = sm;                      // [SROWS][SCOLS] raw x staging
    float* sy = sm + SROWS * SCOLS;      // [SROWS][SCOLS] raw y staging
    float* sh = sm + 2 * SROWS * SCOLS;  // [5][SROWS][TILE_W] H-conv results

    const int tid = threadIdx.x;
    const int bx = blockIdx.x, by = blockIdx.y, p = blockIdx.z;
    const int c0 = bx * TILE_W;
    const int r0 = by * TILE_H;
    const float* px = gx + (size_t)p * IMH * IMW;
    const float* py = gy + (size_t)p * IMH * IMW;

    // ---------------- stage 0: cooperative staging (zero-padded halo) -------
    for (int idx = tid; idx < SROWS * 20; idx += 256) {
        const int i = idx / 20;        // staged row
        const int j4 = idx % 20;       // float4 chunk in row
        const int gr = r0 - 5 + i;
        const int gc = c0 - 8 + j4 * 4;
        float4 vx = make_float4(0.f, 0.f, 0.f, 0.f);
        float4 vy = vx;
        if (gr >= 0 && gr < IMH) {
            const float* rowx = px + (size_t)gr * IMW;
            const float* rowy = py + (size_t)gr * IMW;
            if (gc >= 0 && gc <= IMW - 4) {
                vx = *(const float4*)(rowx + gc);
                vy = *(const float4*)(rowy + gc);
            } else {
                float* fx = (float*)&vx;
                float* fy = (float*)&vy;
                #pragma unroll
                for (int e = 0; e < 4; e++) {
                    const int c = gc + e;
                    if (c >= 0 && c < IMW) { fx[e] = rowx[c]; fy[e] = rowy[c]; }
                }
            }
        }
        *(float4*)(sx + i * SCOLS + j4 * 4) = vx;
        *(float4*)(sy + i * SCOLS + j4 * 4) = vy;
    }
    __syncthreads();

    // ---------------- stage 1: horizontal conv, 4 cols per thread ----------
    {
        const int tx = tid & 15;   // column group (4 cols each -> 64 cols)
        const int ty = tid >> 4;   // row within pass (16 rows per pass)
        const int cb = tx * 4;     // intermediate col base, 0..60
        for (int i = ty; i < SROWS; i += 16) {
            const float* rx = sx + i * SCOLS + cb;
            const float* ry = sy + i * SCOLS + cb;
            // window for outputs cb..cb+3 spans staged cols cb+3..cb+16
            float xq[20], yq[20];
            #pragma unroll
            for (int j = 0; j < 5; j++) {
                float4 v = *(const float4*)(rx + 4 * j);
                xq[4 * j + 0] = v.x; xq[4 * j + 1] = v.y;
                xq[4 * j + 2] = v.z; xq[4 * j + 3] = v.w;
                float4 w = *(const float4*)(ry + 4 * j);
                yq[4 * j + 0] = w.x; yq[4 * j + 1] = w.y;
                yq[4 * j + 2] = w.z; yq[4 * j + 3] = w.w;
            }
            float acx[4]  = {0.f, 0.f, 0.f, 0.f};
            float acy[4]  = {0.f, 0.f, 0.f, 0.f};
            float acxx[4] = {0.f, 0.f, 0.f, 0.f};
            float acyy[4] = {0.f, 0.f, 0.f, 0.f};
            float acxy[4] = {0.f, 0.f, 0.f, 0.f};
            #pragma unroll
            for (int t = 0; t < 11; t++) {
                #pragma unroll
                for (int cc = 0; cc < 4; cc++) {
                    acx[cc] = fmaf(xq[cc + 3 + t], Gw[t], acx[cc]);
                    acy[cc] = fmaf(yq[cc + 3 + t], Gw[t], acy[cc]);
                }
            }
            float pr[14];
            #pragma unroll
            for (int k = 0; k < 14; k++) pr[k] = xq[k + 3] * xq[k + 3];
            #pragma unroll
            for (int t = 0; t < 11; t++)
                #pragma unroll
                for (int cc = 0; cc < 4; cc++)
                    acxx[cc] = fmaf(pr[cc + t], Gw[t], acxx[cc]);
            #pragma unroll
            for (int k = 0; k < 14; k++) pr[k] = yq[k + 3] * yq[k + 3];
            #pragma unroll
            for (int t = 0; t < 11; t++)
                #pragma unroll
                for (int cc = 0; cc < 4; cc++)
                    acyy[cc] = fmaf(pr[cc + t], Gw[t], acyy[cc]);
            #pragma unroll
            for (int k = 0; k < 14; k++) pr[k] = xq[k + 3] * yq[k + 3];
            #pragma unroll
            for (int t = 0; t < 11; t++)
                #pragma unroll
                for (int cc = 0; cc < 4; cc++)
                    acxy[cc] = fmaf(pr[cc + t], Gw[t], acxy[cc]);

            float* hb = sh + i * TILE_W + cb;
            *(float4*)(hb + 0 * HSTRIDE) = make_float4(acx[0],  acx[1],  acx[2],  acx[3]);
            *(float4*)(hb + 1 * HSTRIDE) = make_float4(acy[0],  acy[1],  acy[2],  acy[3]);
            *(float4*)(hb + 2 * HSTRIDE) = make_float4(acxx[0], acxx[1], acxx[2], acxx[3]);
            *(float4*)(hb + 3 * HSTRIDE) = make_float4(acyy[0], acyy[1], acyy[2], acyy[3]);
            *(float4*)(hb + 4 * HSTRIDE) = make_float4(acxy[0], acxy[1], acxy[2], acxy[3]);
        }
    }
    __syncthreads();

    // ---------------- stage 2: vertical conv (8-row strip in regs) + SSIM --
    const int col = tid & 63;
    const int sgrp = tid >> 6;  // 0..3, strip of 8 output rows
    float acc[5][8];
    #pragma unroll
    for (int q = 0; q < 5; q++)
        #pragma unroll
        for (int i = 0; i < 8; i++) acc[q][i] = 0.f;

    #pragma unroll
    for (int jr = 0; jr < 18; jr++) {   // h rows sgrp*8 .. sgrp*8+17
        const int hr = sgrp * 8 + jr;
        float v[5];
        #pragma unroll
        for (int q = 0; q < 5; q++) v[q] = sh[q * HSTRIDE + hr * TILE_W + col];
        #pragma unroll
        for (int i = 0; i < 8; i++) {
            const int t = jr - i;
            if (t >= 0 && t < 11) {
                #pragma unroll
                for (int q = 0; q < 5; q++)
                    acc[q][i] = fmaf(v[q], Gw[t], acc[q][i]);
            }
        }
    }

    float lsum = 0.f;
    #pragma unroll
    for (int i = 0; i < 8; i++) {
        const float mux = acc[0][i], muy = acc[1][i];
        const float exx = acc[2][i], eyy = acc[3][i], exy = acc[4][i];
        const float mux2 = mux * mux;
        const float muy2 = muy * muy;
        const float muxy = mux * muy;
        const float sx2 = exx - mux2;
        const float sy2 = eyy - muy2;
        const float sxy = exy - muxy;
        const float num = (2.f * muxy + 1e-4f) * (2.f * sxy + 9e-4f);
        const float den = (mux2 + muy2 + 1e-4f) * (sx2 + sy2 + 9e-4f) + 1e-12f;
        lsum += 1.f - __fdividef(num, den);
    }

    // block reduction of the 2048 per-pixel losses
    #pragma unroll
    for (int o = 16; o > 0; o >>= 1)
        lsum += __shfl_down_sync(0xffffffffu, lsum, o);
    if ((tid & 31) == 0) sm[tid >> 5] = lsum;   // reuse sx row 0 (stage2 only reads sh)
    __syncthreads();
    if (tid == 0) {
        float s = 0.f;
        #pragma unroll
        for (int w = 0; w < 8; w++) s += sm[w];
        g_partials[(p * 16 + by) * 8 + bx] = s;
    }
}

extern "C" __global__ void ssim_reduce(float* __restrict__ out) {
    __shared__ double sd[256];
    double s = 0.0;
    for (int i = threadIdx.x; i < NBLK; i += 256) s += (double)g_partials[i];
    sd[threadIdx.x] = s;
    __syncthreads();
    #pragma unroll
    for (int o = 128; o > 0; o >>= 1) {
        if (threadIdx.x < o) sd[threadIdx.x] += sd[threadIdx.x + o];
        __syncthreads();
    }
    if (threadIdx.x == 0)
        out[0] = (float)(sd[0] * (1.0 / 12582912.0));  // mean over 16*3*512*512
}

extern "C" void kernel_launch(void* const* d_in, const int* in_sizes, int n_in,
                              void* d_out, int out_size) {
    const float* x = (const float*)d_in[0];
    const float* y = (const float*)d_in[1];
    // d_in[2] is the Gaussian window; taps are deterministic and baked in.
    float* out = (float*)d_out;

    cudaFuncSetAttribute(ssim_main, cudaFuncAttributeMaxDynamicSharedMemorySize,
                         SMEM_BYTES);
    dim3 grid(IMW / TILE_W, IMH / TILE_H, 48);  // 8 x 16 x 48 tiles
    ssim_main<<<grid, 256, SMEM_BYTES>>>(x, y);
    ssim_reduce<<<1, 256>>>(out);
}

// round 2
// speedup vs baseline: 1.0430x; 1.0430x over previous
#include <cuda_runtime.h>

// SSIM loss, 16x3x512x512 f32, separable 11-tap Gaussian (sigma=1.5).
// One fused kernel: staged (x,y) pairs -> H-conv of packed {(x,y),(x2,y2)} +
// scalar xy via fma.rn.f32x2 -> V-conv in regs -> SSIM map -> block partials
// -> last-block deterministic reduction. Taps hardcoded (deterministic).

#define IMH 512
#define IMW 512
#define TILE_W 64
#define TILE_H 32
#define SROWS 42            // TILE_H + 10 halo
#define SPITCH 100          // staggered float2 pairs per staged row
#define HP 64               // h-result row width (cols)
#define NBLK (8 * 16 * 48)
#define OFF_A 8400          // floats: staging = 42*100*2
#define OFF_B 13776         // OFF_A + 42*64*2
#define OFF_C 19152         // OFF_B + 42*64*2
#define SMEM_FLOATS 21840   // OFF_C + 42*64
#define SMEM_BYTES (SMEM_FLOATS * 4)

typedef unsigned long long ull;

__device__ float g_partials[NBLK];
__device__ unsigned int g_count = 0;

static __device__ constexpr float Gw[11] = {
    0.00102838f, 0.00759876f, 0.03600078f, 0.10936070f, 0.21300553f,
    0.26601172f,
    0.21300553f, 0.10936070f, 0.03600078f, 0.00759876f, 0.00102838f};

__device__ __forceinline__ ull pk2(float lo, float hi) {
    ull r;
    asm("mov.b64 %0, {%1,%2};" : "=l"(r) : "f"(lo), "f"(hi));
    return r;
}
__device__ __forceinline__ void upk(ull v, float& lo, float& hi) {
    asm("mov.b64 {%0,%1}, %2;" : "=f"(lo), "=f"(hi) : "l"(v));
}
__device__ __forceinline__ ull f2fma(ull a, ull b, ull c) {
    ull d;
    asm("fma.rn.f32x2 %0, %1, %2, %3;" : "=l"(d) : "l"(a), "l"(b), "l"(c));
    return d;
}
__device__ __forceinline__ ull f2mul(ull a, ull b) {
    ull d;
    asm("mul.rn.f32x2 %0, %1, %2;" : "=l"(d) : "l"(a), "l"(b));
    return d;
}

extern "C" __global__ void __launch_bounds__(256, 2)
ssim_main(const float* __restrict__ gx, const float* __restrict__ gy,
          float* __restrict__ out) {
    extern __shared__ float sm[];
    __shared__ int s_last;

    const int tid = threadIdx.x;
    const int bx = blockIdx.x, by = blockIdx.y, p = blockIdx.z;
    const int c0 = bx * TILE_W;
    const int r0 = by * TILE_H;
    const float* px = gx + (size_t)p * IMH * IMW;
    const float* py = gy + (size_t)p * IMH * IMW;

    // packed taps (both halves = tap); compiler hoists/CSEs these
    ull GwP[11];
    #pragma unroll
    for (int t = 0; t < 11; t++) GwP[t] = pk2(Gw[t], Gw[t]);

    // ---------------- stage 0: stage interleaved (x,y) pairs, zero halo ----
    for (int idx = tid; idx < SROWS * 20; idx += 256) {
        const int i = idx / 20;
        const int j4 = idx % 20;
        const int gr = r0 - 5 + i;
        const int gc = c0 - 8 + j4 * 4;
        float4 vx = make_float4(0.f, 0.f, 0.f, 0.f);
        float4 vy = vx;
        if (gr >= 0 && gr < IMH) {
            const float* rowx = px + (size_t)gr * IMW;
            const float* rowy = py + (size_t)gr * IMW;
            if (gc >= 0 && gc <= IMW - 4) {
                vx = *(const float4*)(rowx + gc);
                vy = *(const float4*)(rowy + gc);
            } else {
                float* fx = (float*)&vx;
                float* fy = (float*)&vy;
                #pragma unroll
                for (int e = 0; e < 4; e++) {
                    const int c = gc + e;
                    if (c >= 0 && c < IMW) { fx[e] = rowx[c]; fy[e] = rowy[c]; }
                }
            }
        }
        // staggered pair index: s(col)=col+(col>>2); cols 4*j4..4*j4+3 -> 5*j4..
        float* dst = sm + 2 * (i * SPITCH + 5 * j4);
        ((ull*)dst)[0] = pk2(vx.x, vy.x);
        ((ull*)dst)[1] = pk2(vx.y, vy.y);
        ((ull*)dst)[2] = pk2(vx.z, vy.z);
        ((ull*)dst)[3] = pk2(vx.w, vy.w);
    }
    __syncthreads();

    // ---------------- stage 1: horizontal conv, packed streams -------------
    {
        const int tx = tid & 15;
        const int ty = tid >> 4;
        const int cb = tx * 4;           // output col base
        const int cboff = 5 * tx;        // staggered pair offset of col cb
        for (int i = ty; i < SROWS; i += 16) {
            const float* bp = sm + 2 * (i * SPITCH + cboff);
            ull vp[14];
            #pragma unroll
            for (int k = 0; k < 14; k++) {
                const int kk = k + 3;
                vp[k] = *(const ull*)(bp + 2 * (kk + (kk >> 2)));
            }
            // (mu_x, mu_y) stream
            ull a0 = 0ull, a1 = 0ull, a2 = 0ull, a3 = 0ull;
            #pragma unroll
            for (int t = 0; t < 11; t++) {
                a0 = f2fma(vp[t + 0], GwP[t], a0);
                a1 = f2fma(vp[t + 1], GwP[t], a1);
                a2 = f2fma(vp[t + 2], GwP[t], a2);
                a3 = f2fma(vp[t + 3], GwP[t], a3);
            }
            {
                float* hA = sm + OFF_A + 2 * (i * HP + cb);
                ((ulonglong2*)hA)[0] = make_ulonglong2(a0, a1);
                ((ulonglong2*)hA)[1] = make_ulonglong2(a2, a3);
            }
            // (x^2, y^2) stream
            ull sq[14];
            #pragma unroll
            for (int k = 0; k < 14; k++) sq[k] = f2mul(vp[k], vp[k]);
            ull b0 = 0ull, b1 = 0ull, b2 = 0ull, b3 = 0ull;
            #pragma unroll
            for (int t = 0; t < 11; t++) {
                b0 = f2fma(sq[t + 0], GwP[t], b0);
                b1 = f2fma(sq[t + 1], GwP[t], b1);
                b2 = f2fma(sq[t + 2], GwP[t], b2);
                b3 = f2fma(sq[t + 3], GwP[t], b3);
            }
            {
                float* hB = sm + OFF_B + 2 * (i * HP + cb);
                ((ulonglong2*)hB)[0] = make_ulonglong2(b0, b1);
                ((ulonglong2*)hB)[1] = make_ulonglong2(b2, b3);
            }
            // x*y scalar stream
            float cr[14];
            #pragma unroll
            for (int k = 0; k < 14; k++) {
                float lo, hi;
                upk(vp[k], lo, hi);
                cr[k] = lo * hi;
            }
            float c0a = 0.f, c1a = 0.f, c2a = 0.f, c3a = 0.f;
            #pragma unroll
            for (int t = 0; t < 11; t++) {
                c0a = fmaf(cr[t + 0], Gw[t], c0a);
                c1a = fmaf(cr[t + 1], Gw[t], c1a);
                c2a = fmaf(cr[t + 2], Gw[t], c2a);
                c3a = fmaf(cr[t + 3], Gw[t], c3a);
            }
            *(float4*)(sm + OFF_C + i * HP + cb) = make_float4(c0a, c1a, c2a, c3a);
        }
    }
    __syncthreads();

    // ---------------- stage 2: vertical conv (8-row strip) + SSIM ----------
    const int col = tid & 63;
    const int sgrp = tid >> 6;
    ull aA[8], aB[8];
    float aC[8];
    #pragma unroll
    for (int i = 0; i < 8; i++) { aA[i] = 0ull; aB[i] = 0ull; aC[i] = 0.f; }

    #pragma unroll
    for (int jr = 0; jr < 18; jr++) {
        const int hr = sgrp * 8 + jr;
        const ull vA = *(const ull*)(sm + OFF_A + 2 * (hr * HP + col));
        const ull vB = *(const ull*)(sm + OFF_B + 2 * (hr * HP + col));
        const float vC = sm[OFF_C + hr * HP + col];
        #pragma unroll
        for (int i = 0; i < 8; i++) {
            const int t = jr - i;
            if (t >= 0 && t < 11) {
                aA[i] = f2fma(vA, GwP[t], aA[i]);
                aB[i] = f2fma(vB, GwP[t], aB[i]);
                aC[i] = fmaf(vC, Gw[t], aC[i]);
            }
        }
    }

    float lsum = 0.f;
    #pragma unroll
    for (int i = 0; i < 8; i++) {
        float mux, muy, exx, eyy;
        upk(aA[i], mux, muy);
        upk(aB[i], exx, eyy);
        const float exy = aC[i];
        const float mux2 = mux * mux;
        const float muy2 = muy * muy;
        const float muxy = mux * muy;
        const float sx2 = exx - mux2;
        const float sy2 = eyy - muy2;
        const float sxy = exy - muxy;
        const float num = (2.f * muxy + 1e-4f) * (2.f * sxy + 9e-4f);
        const float den = (mux2 + muy2 + 1e-4f) * (sx2 + sy2 + 9e-4f) + 1e-12f;
        lsum += 1.f - __fdividef(num, den);
    }

    #pragma unroll
    for (int o = 16; o > 0; o >>= 1)
        lsum += __shfl_down_sync(0xffffffffu, lsum, o);
    if ((tid & 31) == 0) sm[tid >> 5] = lsum;
    __syncthreads();
    if (tid == 0) {
        float s = 0.f;
        #pragma unroll
        for (int w = 0; w < 8; w++) s += sm[w];
        g_partials[(p * 16 + by) * 8 + bx] = s;
        __threadfence();
        const unsigned int old = atomicAdd(&g_count, 1u);
        s_last = (old == NBLK - 1) ? 1 : 0;
    }
    __syncthreads();

    // ---------------- last block: deterministic final reduction ------------
    if (s_last) {
        double s = 0.0;
        for (int i = tid; i < NBLK; i += 256) s += (double)g_partials[i];
        double* sd = (double*)sm;
        sd[tid] = s;
        __syncthreads();
        #pragma unroll
        for (int o = 128; o > 0; o >>= 1) {
            if (tid < o) sd[tid] += sd[tid + o];
            __syncthreads();
        }
        if (tid == 0) {
            out[0] = (float)(sd[0] * (1.0 / 12582912.0));
            g_count = 0;  // reset for next graph replay
        }
    }
}

extern "C" void kernel_launch(void* const* d_in, const int* in_sizes, int n_in,
                              void* d_out, int out_size) {
    const float* x = (const float*)d_in[0];
    const float* y = (const float*)d_in[1];
    float* out = (float*)d_out;

    cudaFuncSetAttribute(ssim_main, cudaFuncAttributeMaxDynamicSharedMemorySize,
                         SMEM_BYTES);
    dim3 grid(IMW / TILE_W, IMH / TILE_H, 48);
    ssim_main<<<grid, 256, SMEM_BYTES>>>(x, y, out);
}

// round 4
// speedup vs baseline: 1.3692x; 1.3128x over previous
#include <cuda_runtime.h>

// SSIM loss, 16x3x512x512 f32, separable 11-tap Gaussian (sigma=1.5).
// Fused kernel: H-conv loads raw (x,y) straight from global (L1-hit halo),
// packed {(x,y),(x2,y2)} + scalar xy via fma.rn.f32x2 into smem planes,
// V-conv in regs, SSIM map, block partials, last-block reduction.
// Smem = 53.8KB/block -> 4 resident blocks/SM (was 2 at 87KB).

#define IMH 512
#define IMW 512
#define TILE_W 64
#define TILE_H 32
#define SROWS 42            // TILE_H + 10 halo
#define HP 64               // h-result row width (cols)
#define NBLK (8 * 16 * 48)
#define OFF_A 0
#define OFF_B (SROWS * HP * 2)          // 5376 floats
#define OFF_C (2 * SROWS * HP * 2)      // 10752 floats
#define SMEM_FLOATS (OFF_C + SROWS * HP)  // 13440
#define SMEM_BYTES (SMEM_FLOATS * 4)      // 53760

typedef unsigned long long ull;

__device__ float g_partials[NBLK];
__device__ unsigned int g_count = 0;

static __device__ constexpr float Gw[11] = {
    0.00102838f, 0.00759876f, 0.03600078f, 0.10936070f, 0.21300553f,
    0.26601172f,
    0.21300553f, 0.10936070f, 0.03600078f, 0.00759876f, 0.00102838f};

__device__ __forceinline__ ull pk2(float lo, float hi) {
    ull r;
    asm("mov.b64 %0, {%1,%2};" : "=l"(r) : "f"(lo), "f"(hi));
    return r;
}
__device__ __forceinline__ void upk(ull v, float& lo, float& hi) {
    asm("mov.b64 {%0,%1}, %2;" : "=f"(lo), "=f"(hi) : "l"(v));
}
__device__ __forceinline__ ull f2fma(ull a, ull b, ull c) {
    ull d;
    asm("fma.rn.f32x2 %0, %1, %2, %3;" : "=l"(d) : "l"(a), "l"(b), "l"(c));
    return d;
}
__device__ __forceinline__ ull f2mul(ull a, ull b) {
    ull d;
    asm("mul.rn.f32x2 %0, %1, %2;" : "=l"(d) : "l"(a), "l"(b));
    return d;
}

extern "C" __global__ void __launch_bounds__(256, 4)
ssim_main(const float* __restrict__ gx, const float* __restrict__ gy,
          float* __restrict__ out) {
    extern __shared__ float sm[];
    __shared__ int s_last;

    const int tid = threadIdx.x;
    const int bx = blockIdx.x, by = blockIdx.y, p = blockIdx.z;
    const int c0 = bx * TILE_W;
    const int r0 = by * TILE_H;
    const float* px = gx + (size_t)p * IMH * IMW;
    const float* py = gy + (size_t)p * IMH * IMW;

    ull GwP[11];
    #pragma unroll
    for (int t = 0; t < 11; t++) GwP[t] = pk2(Gw[t], Gw[t]);

    // ---------------- stage 1: horizontal conv, raw loads from global -----
    {
        const int tx = tid & 15;
        const int ty = tid >> 4;
        const int cb = tx * 4;               // output col base in tile
        const int gc0 = c0 + cb - 8;         // first loaded col (float4-aligned)
        const bool colsafe = (gc0 >= 0) && (gc0 + 19 < IMW);

        for (int i = ty; i < SROWS; i += 16) {
            const int gr = r0 - 5 + i;
            float xq[20], yq[20];
            if (gr >= 0 && gr < IMH) {
                const float* rowx = px + (size_t)gr * IMW;
                const float* rowy = py + (size_t)gr * IMW;
                if (colsafe) {
                    #pragma unroll
                    for (int j = 0; j < 5; j++) {
                        float4 v = *(const float4*)(rowx + gc0 + 4 * j);
                        xq[4 * j + 0] = v.x; xq[4 * j + 1] = v.y;
                        xq[4 * j + 2] = v.z; xq[4 * j + 3] = v.w;
                        float4 w = *(const float4*)(rowy + gc0 + 4 * j);
                        yq[4 * j + 0] = w.x; yq[4 * j + 1] = w.y;
                        yq[4 * j + 2] = w.z; yq[4 * j + 3] = w.w;
                    }
                } else {
                    #pragma unroll
                    for (int e = 0; e < 20; e++) {
                        const int c = gc0 + e;
                        const bool ok = (c >= 0) && (c < IMW);
                        xq[e] = ok ? rowx[c] : 0.f;
                        yq[e] = ok ? rowy[c] : 0.f;
                    }
                }
            } else {
                #pragma unroll
                for (int e = 0; e < 20; e++) { xq[e] = 0.f; yq[e] = 0.f; }
            }

            ull vp[14];
            #pragma unroll
            for (int k = 0; k < 14; k++) vp[k] = pk2(xq[k + 3], yq[k + 3]);

            // (mu_x, mu_y) stream
            ull a0 = 0ull, a1 = 0ull, a2 = 0ull, a3 = 0ull;
            #pragma unroll
            for (int t = 0; t < 11; t++) {
                a0 = f2fma(vp[t + 0], GwP[t], a0);
                a1 = f2fma(vp[t + 1], GwP[t], a1);
                a2 = f2fma(vp[t + 2], GwP[t], a2);
                a3 = f2fma(vp[t + 3], GwP[t], a3);
            }
            {
                float* hA = sm + OFF_A + 2 * (i * HP + cb);
                ((ulonglong2*)hA)[0] = make_ulonglong2(a0, a1);
                ((ulonglong2*)hA)[1] = make_ulonglong2(a2, a3);
            }
            // x*y scalar stream (from vp before squaring)
            float cr[14];
            #pragma unroll
            for (int k = 0; k < 14; k++) {
                float lo, hi;
                upk(vp[k], lo, hi);
                cr[k] = lo * hi;
            }
            // (x^2, y^2): square vp in place
            #pragma unroll
            for (int k = 0; k < 14; k++) vp[k] = f2mul(vp[k], vp[k]);
            ull b0 = 0ull, b1 = 0ull, b2 = 0ull, b3 = 0ull;
            #pragma unroll
            for (int t = 0; t < 11; t++) {
                b0 = f2fma(vp[t + 0], GwP[t], b0);
                b1 = f2fma(vp[t + 1], GwP[t], b1);
                b2 = f2fma(vp[t + 2], GwP[t], b2);
                b3 = f2fma(vp[t + 3], GwP[t], b3);
            }
            {
                float* hB = sm + OFF_B + 2 * (i * HP + cb);
                ((ulonglong2*)hB)[0] = make_ulonglong2(b0, b1);
                ((ulonglong2*)hB)[1] = make_ulonglong2(b2, b3);
            }
            float c0a = 0.f, c1a = 0.f, c2a = 0.f, c3a = 0.f;
            #pragma unroll
            for (int t = 0; t < 11; t++) {
                c0a = fmaf(cr[t + 0], Gw[t], c0a);
                c1a = fmaf(cr[t + 1], Gw[t], c1a);
                c2a = fmaf(cr[t + 2], Gw[t], c2a);
                c3a = fmaf(cr[t + 3], Gw[t], c3a);
            }
            *(float4*)(sm + OFF_C + i * HP + cb) = make_float4(c0a, c1a, c2a, c3a);
        }
    }
    __syncthreads();

    // ---------------- stage 2: vertical conv (8-row strip) + SSIM ----------
    const int col = tid & 63;
    const int sgrp = tid >> 6;
    ull aA[8], aB[8];
    float aC[8];
    #pragma unroll
    for (int i = 0; i < 8; i++) { aA[i] = 0ull; aB[i] = 0ull; aC[i] = 0.f; }

    #pragma unroll
    for (int jr = 0; jr < 18; jr++) {
        const int hr = sgrp * 8 + jr;
        const ull vA = *(const ull*)(sm + OFF_A + 2 * (hr * HP + col));
        const ull vB = *(const ull*)(sm + OFF_B + 2 * (hr * HP + col));
        const float vC = sm[OFF_C + hr * HP + col];
        #pragma unroll
        for (int i = 0; i < 8; i++) {
            const int t = jr - i;
            if (t >= 0 && t < 11) {
                aA[i] = f2fma(vA, GwP[t], aA[i]);
                aB[i] = f2fma(vB, GwP[t], aB[i]);
                aC[i] = fmaf(vC, Gw[t], aC[i]);
            }
        }
    }

    float lsum = 0.f;
    #pragma unroll
    for (int i = 0; i < 8; i++) {
        float mux, muy, exx, eyy;
        upk(aA[i], mux, muy);
        upk(aB[i], exx, eyy);
        const float exy = aC[i];
        const float mux2 = mux * mux;
        const float muy2 = muy * muy;
        const float muxy = mux * muy;
        const float sx2 = exx - mux2;
        const float sy2 = eyy - muy2;
        const float sxy = exy - muxy;
        const float num = (2.f * muxy + 1e-4f) * (2.f * sxy + 9e-4f);
        const float den = (mux2 + muy2 + 1e-4f) * (sx2 + sy2 + 9e-4f) + 1e-12f;
        lsum += 1.f - __fdividef(num, den);
    }

    __syncthreads();   // stage-2 smem reads complete before reuse below
    #pragma unroll
    for (int o = 16; o > 0; o >>= 1)
        lsum += __shfl_down_sync(0xffffffffu, lsum, o);
    if ((tid & 31) == 0) sm[tid >> 5] = lsum;
    __syncthreads();
    if (tid == 0) {
        float s = 0.f;
        #pragma unroll
        for (int w = 0; w < 8; w++) s += sm[w];
        g_partials[(p * 16 + by) * 8 + bx] = s;
        __threadfence();
        const unsigned int old = atomicAdd(&g_count, 1u);
        s_last = (old == NBLK - 1) ? 1 : 0;
    }
    __syncthreads();

    // ---------------- last block: deterministic final reduction ------------
    if (s_last) {
        double s = 0.0;
        for (int i = tid; i < NBLK; i += 256) s += (double)g_partials[i];
        double* sd = (double*)sm;
        sd[tid] = s;
        __syncthreads();
        #pragma unroll
        for (int o = 128; o > 0; o >>= 1) {
            if (tid < o) sd[tid] += sd[tid + o];
            __syncthreads();
        }
        if (tid == 0) {
            out[0] = (float)(sd[0] * (1.0 / 12582912.0));
            g_count = 0;  // reset for next graph replay
        }
    }
}

extern "C" void kernel_launch(void* const* d_in, const int* in_sizes, int n_in,
                              void* d_out, int out_size) {
    const float* x = (const float*)d_in[0];
    const float* y = (const float*)d_in[1];
    float* out = (float*)d_out;

    cudaFuncSetAttribute(ssim_main, cudaFuncAttributeMaxDynamicSharedMemorySize,
                         SMEM_BYTES);
    dim3 grid(IMW / TILE_W, IMH / TILE_H, 48);
    ssim_main<<<grid, 256, SMEM_BYTES>>>(x, y, out);
}